// round 10
// baseline (speedup 1.0000x reference)
#include <cuda_runtime.h>
#include <cuda_bf16.h>
#include <math.h>
#include <stdint.h>

// Problem constants
#define TOKENS 2048
#define HID 256
#define NB 41
#define CBIN 123
#define OUTC (CBIN * HID)    // 31488
#define OPT (NB * NB * NB)   // 68921
#define NXZ (NB * NB)        // 1681

#define CHUNKS 8
#define TOK_PER_CHUNK (TOKENS / CHUNKS)      // 256
#define TT_PER_CHUNK (TOK_PER_CHUNK / 128)   // 2 t-tiles

// Scratch: bin = softplus(emb @ W^T + b), token-major bf16
__device__ __nv_bfloat16 g_bin[(size_t)TOKENS * OUTC];

// ---------------------------------------------------------------------------
// Shared helpers
// ---------------------------------------------------------------------------
__device__ __forceinline__ uint32_t pack_bf16(float a, float b) {
    __nv_bfloat162 t = __float22bfloat162_rn(make_float2(a, b));
    return *(uint32_t*)&t;
}
__device__ __forceinline__ void mma16816(float* d,
                                         uint32_t a0, uint32_t a1,
                                         uint32_t a2, uint32_t a3,
                                         uint32_t b0, uint32_t b1) {
    asm volatile(
        "mma.sync.aligned.m16n8k16.row.col.f32.bf16.bf16.f32 "
        "{%0,%1,%2,%3}, {%4,%5,%6,%7}, {%8,%9}, {%0,%1,%2,%3};"
        : "+f"(d[0]), "+f"(d[1]), "+f"(d[2]), "+f"(d[3])
        : "r"(a0), "r"(a1), "r"(a2), "r"(a3), "r"(b0), "r"(b1));
}
__device__ __forceinline__ float softplusf(float x) {
    return fmaxf(x, 0.0f) + log1pf(expf(-fabsf(x)));
}

// ---------------------------------------------------------------------------
// Stage 1: bf16 tensor-core GEMM + softplus + bf16 store (round-9 kernel,
// plus a t-tile base offset so it can be launched per token chunk)
// ---------------------------------------------------------------------------
#define RS1 12    // SMEM row stride in u32

__global__ void __launch_bounds__(256, 2) gemm_softplus_bf16(
    const float* __restrict__ W, const float* __restrict__ emb,
    const float* __restrict__ bias, int ttile0)
{
    __shared__ uint32_t As[2][128 * RS1];
    __shared__ uint32_t Bs[2][128 * RS1];

    const int t0 = (blockIdx.y + ttile0) * 128;
    const int o0 = blockIdx.x * 128;
    const int tid = threadIdx.x;
    const int wid = tid >> 5, lane = tid & 31;
    const int wm = (wid & 1) * 64;
    const int wn = (wid >> 1) * 32;
    const int r = lane >> 2, qc = lane & 3;

    const int lrow = tid >> 1;
    const int q0 = (tid & 1) * 4;
    const int q1 = q0 + 8;
    const int uc0 = q0 >> 1;
    const int uc1 = q1 >> 1;
    const float* embRow = emb + (size_t)(t0 + lrow) * HID;
    const float* wRow = W + (size_t)(o0 + lrow) * HID;

    float acc[4][4][4];
    #pragma unroll
    for (int mt = 0; mt < 4; mt++)
        #pragma unroll
        for (int nt = 0; nt < 4; nt++)
            #pragma unroll
            for (int q = 0; q < 4; q++) acc[mt][nt][q] = 0.0f;

    {
        float4 ea = *(const float4*)(embRow + q0);
        float4 eb = *(const float4*)(embRow + q1);
        float4 wa = *(const float4*)(wRow + q0);
        float4 wb = *(const float4*)(wRow + q1);
        uint32_t* ap = &As[0][lrow * RS1];
        uint32_t* bp = &Bs[0][lrow * RS1];
        ap[uc0] = pack_bf16(ea.x, ea.y); ap[uc0 + 1] = pack_bf16(ea.z, ea.w);
        ap[uc1] = pack_bf16(eb.x, eb.y); ap[uc1 + 1] = pack_bf16(eb.z, eb.w);
        bp[uc0] = pack_bf16(wa.x, wa.y); bp[uc0 + 1] = pack_bf16(wa.z, wa.w);
        bp[uc1] = pack_bf16(wb.x, wb.y); bp[uc1 + 1] = pack_bf16(wb.z, wb.w);
    }
    __syncthreads();

    float4 ea, eb, wa, wb;
    #pragma unroll 1
    for (int it = 0; it < 16; it++) {
        const int cur = it & 1;
        if (it < 15) {
            const int k0 = (it + 1) * 16;
            ea = *(const float4*)(embRow + k0 + q0);
            eb = *(const float4*)(embRow + k0 + q1);
            wa = *(const float4*)(wRow + k0 + q0);
            wb = *(const float4*)(wRow + k0 + q1);
        }

        const uint32_t* Ac = As[cur];
        const uint32_t* Bc = Bs[cur];
        uint32_t a[4][4], b[4][2];
        #pragma unroll
        for (int mt = 0; mt < 4; mt++) {
            const uint32_t* p = &Ac[(wm + mt * 16 + r) * RS1];
            a[mt][0] = p[qc];
            a[mt][1] = p[8 * RS1 + qc];
            a[mt][2] = p[qc + 4];
            a[mt][3] = p[8 * RS1 + qc + 4];
        }
        #pragma unroll
        for (int nt = 0; nt < 4; nt++) {
            const uint32_t* p = &Bc[(wn + nt * 8 + r) * RS1];
            b[nt][0] = p[qc];
            b[nt][1] = p[qc + 4];
        }
        #pragma unroll
        for (int mt = 0; mt < 4; mt++)
            #pragma unroll
            for (int nt = 0; nt < 4; nt++)
                mma16816(acc[mt][nt], a[mt][0], a[mt][1], a[mt][2], a[mt][3],
                         b[nt][0], b[nt][1]);

        if (it < 15) {
            const int nxt = cur ^ 1;
            uint32_t* ap = &As[nxt][lrow * RS1];
            uint32_t* bp = &Bs[nxt][lrow * RS1];
            ap[uc0] = pack_bf16(ea.x, ea.y); ap[uc0 + 1] = pack_bf16(ea.z, ea.w);
            ap[uc1] = pack_bf16(eb.x, eb.y); ap[uc1 + 1] = pack_bf16(eb.z, eb.w);
            bp[uc0] = pack_bf16(wa.x, wa.y); bp[uc0 + 1] = pack_bf16(wa.z, wa.w);
            bp[uc1] = pack_bf16(wb.x, wb.y); bp[uc1 + 1] = pack_bf16(wb.z, wb.w);
            __syncthreads();
        }
    }

    uint32_t* gb = (uint32_t*)g_bin;
    #pragma unroll
    for (int mt = 0; mt < 4; mt++) {
        const int tA = t0 + wm + mt * 16 + r;
        const size_t row0 = (size_t)tA * (OUTC / 2);
        const size_t row1 = (size_t)(tA + 8) * (OUTC / 2);
        #pragma unroll
        for (int nt = 0; nt < 4; nt++) {
            const int o = o0 + wn + nt * 8 + 2 * qc;
            const float2 bi = *(const float2*)(bias + o);
            float s0 = softplusf(acc[mt][nt][0] + bi.x);
            float s1 = softplusf(acc[mt][nt][1] + bi.y);
            float s2 = softplusf(acc[mt][nt][2] + bi.x);
            float s3 = softplusf(acc[mt][nt][3] + bi.y);
            gb[row0 + (o >> 1)] = pack_bf16(s0, s1);
            gb[row1 + (o >> 1)] = pack_bf16(s2, s3);
        }
    }
}

// ---------------------------------------------------------------------------
// Stage 2: per-token triple contraction (round-9 kernel + token base offset)
// ---------------------------------------------------------------------------
#define RS 132
#define EYB 41
#define EZB 89
#define SM2_U32 (137 * RS)
#define SM2_BYTES (SM2_U32 * 4)   // 72336

__device__ __forceinline__ uint32_t bmul2(uint32_t a, uint32_t b) {
    uint32_t d;
    asm("mul.bf16x2 %0, %1, %2;" : "=r"(d) : "r"(a), "r"(b));
    return d;
}

__global__ void __launch_bounds__(256, 2) triple_mma_kernel(
    const float* __restrict__ ls, float* __restrict__ out, int tbase)
{
    extern __shared__ uint32_t sm[];
    const int tid = threadIdx.x;
    const int wid = tid >> 5;
    const int lid = tid & 31;
    const int rowin = lid >> 2;
    const int qc = lid & 3;
    const int t = blockIdx.x + tbase;

    const uint4* src = (const uint4*)(g_bin + (size_t)t * OUTC);
    for (int i = tid; i < CBIN * 32; i += 256) {
        const int cc = i >> 5;
        const int j = i & 31;
        const int dr = cc + (cc >= 82 ? 7 : 0);
        *(uint4*)&sm[dr * RS + j * 4] = src[i];
    }
    for (int i = tid; i < 7 * RS; i += 256) {
        sm[82 * RS + i] = 0u;
        sm[130 * RS + i] = 0u;
    }
    __syncthreads();

    const float scale = expf(ls[0]);
    float* __restrict__ outT = out + (size_t)t * OPT;

    for (int j = wid; j < 63; j += 8) {
        const int zt = j / 21;
        const int xp = j - zt * 21;
        const int x0 = 2 * xp;
        const bool hasx1 = (x0 + 1 < NB);
        const int x1 = hasx1 ? (x0 + 1) : (NB - 1);
        const int z0 = zt * 16;

        float acc[2][6][4];
        #pragma unroll
        for (int xi = 0; xi < 2; xi++)
            #pragma unroll
            for (int g = 0; g < 6; g++)
                #pragma unroll
                for (int qq = 0; qq < 4; qq++) acc[xi][g][qq] = 0.0f;

        const uint32_t* __restrict__ ex0p = sm + x0 * RS;
        const uint32_t* __restrict__ ex1p = sm + x1 * RS;
        const uint32_t* __restrict__ ezA = sm + (EZB + z0 + rowin) * RS;
        const uint32_t* __restrict__ ezB = ezA + 8 * RS;
        const uint32_t* __restrict__ eyp = sm + (EYB + rowin) * RS;

        #pragma unroll
        for (int k = 0; k < 16; k++) {
            const int c0 = k * 8 + qc;
            const int c1 = c0 + 4;
            const uint32_t ez0 = ezA[c0], ez1 = ezB[c0];
            const uint32_t ez2 = ezA[c1], ez3 = ezB[c1];
            const uint32_t exa0 = ex0p[c0], exa1 = ex0p[c1];
            const uint32_t exb0 = ex1p[c0], exb1 = ex1p[c1];
            const uint32_t A00 = bmul2(ez0, exa0), A01 = bmul2(ez1, exa0);
            const uint32_t A02 = bmul2(ez2, exa1), A03 = bmul2(ez3, exa1);
            const uint32_t A10 = bmul2(ez0, exb0), A11 = bmul2(ez1, exb0);
            const uint32_t A12 = bmul2(ez2, exb1), A13 = bmul2(ez3, exb1);
            #pragma unroll
            for (int g = 0; g < 6; g++) {
                const uint32_t b0 = eyp[g * 8 * RS + c0];
                const uint32_t b1 = eyp[g * 8 * RS + c1];
                mma16816(acc[0][g], A00, A01, A02, A03, b0, b1);
                mma16816(acc[1][g], A10, A11, A12, A13, b0, b1);
            }
        }

        const int zlo = z0 + rowin;
        const int zhi = zlo + 8;
        #pragma unroll
        for (int xi = 0; xi < 2; xi++) {
            if (xi == 1 && !hasx1) break;
            const int x = xi ? x1 : x0;
            float* const obase = outT + x * NB;
            #pragma unroll
            for (int g = 0; g < 6; g++) {
                const int y = 8 * g + 2 * qc;
                if (y < NB) {
                    obase[(size_t)y * NXZ + zlo] = acc[xi][g][0] * scale;
                    if (zhi < NB) obase[(size_t)y * NXZ + zhi] = acc[xi][g][2] * scale;
                }
                if (y + 1 < NB) {
                    obase[(size_t)(y + 1) * NXZ + zlo] = acc[xi][g][1] * scale;
                    if (zhi < NB) obase[(size_t)(y + 1) * NXZ + zhi] = acc[xi][g][3] * scale;
                }
            }
        }
    }
}

// ---------------------------------------------------------------------------
// Launch: 8-chunk software pipeline across two streams (fork/join via events
// — the documented graph-capture pattern). Stage-1 chunk c feeds stage-2
// chunk c; stage-2 chunk c overlaps stage-1 chunk c+1.
// ---------------------------------------------------------------------------
extern "C" void kernel_launch(void* const* d_in, const int* in_sizes, int n_in,
                              void* d_out, int out_size)
{
    const float *emb = nullptr, *W = nullptr, *bias = nullptr, *ls = nullptr;
    for (int i = 0; i < n_in; i++) {
        switch (in_sizes[i]) {
            case TOKENS * HID:   emb  = (const float*)d_in[i]; break;
            case OUTC * HID:     W    = (const float*)d_in[i]; break;
            case OUTC:           bias = (const float*)d_in[i]; break;
            case 1:              ls   = (const float*)d_in[i]; break;
            default: break;
        }
    }

    cudaFuncSetAttribute(triple_mma_kernel,
                         cudaFuncAttributeMaxDynamicSharedMemorySize,
                         SM2_BYTES);

    cudaStream_t sB;
    cudaStreamCreateWithFlags(&sB, cudaStreamNonBlocking);
    cudaEvent_t ev[CHUNKS], evJoin;
    for (int c = 0; c < CHUNKS; c++)
        cudaEventCreateWithFlags(&ev[c], cudaEventDisableTiming);
    cudaEventCreateWithFlags(&evJoin, cudaEventDisableTiming);

    dim3 g1(OUTC / 128, TT_PER_CHUNK);   // 246 x 2 per chunk
    for (int c = 0; c < CHUNKS; c++) {
        gemm_softplus_bf16<<<g1, 256>>>(W, emb, bias, c * TT_PER_CHUNK);
        cudaEventRecord(ev[c], (cudaStream_t)0);
        cudaStreamWaitEvent(sB, ev[c], 0);
        triple_mma_kernel<<<TOK_PER_CHUNK, 256, SM2_BYTES, sB>>>(
            ls, (float*)d_out, c * TOK_PER_CHUNK);
    }
    cudaEventRecord(evJoin, sB);
    cudaStreamWaitEvent((cudaStream_t)0, evJoin, 0);
    // Streams/events intentionally not destroyed: kernel_launch is called at
    // most twice (correctness + capture) and the graph retains the fork/join
    // edges; destroying capture-referenced objects mid-capture is unsafe.
}

// round 11
// speedup vs baseline: 1.1855x; 1.1855x over previous
#include <cuda_runtime.h>
#include <cuda_bf16.h>
#include <math.h>
#include <stdint.h>

// Problem constants
#define TOKENS 2048
#define HID 256
#define NB 41
#define CBIN 123
#define OUTC (CBIN * HID)    // 31488
#define OPT (NB * NB * NB)   // 68921
#define NXZ (NB * NB)        // 1681

// Scratch
__device__ __nv_bfloat16 g_bin[(size_t)TOKENS * OUTC];   // stage-1 output
__device__ __nv_bfloat16 g_wbf[(size_t)OUTC * HID];      // W in bf16
__device__ __nv_bfloat16 g_ebf[(size_t)TOKENS * HID];    // emb in bf16

// ---------------------------------------------------------------------------
// Helpers
// ---------------------------------------------------------------------------
__device__ __forceinline__ uint32_t pack_bf16(float a, float b) {
    __nv_bfloat162 t = __float22bfloat162_rn(make_float2(a, b));
    return *(uint32_t*)&t;
}
__device__ __forceinline__ uint32_t smem_u32(const void* p) {
    uint32_t a;
    asm("{ .reg .u64 t; cvta.to.shared.u64 t, %1; cvt.u32.u64 %0, t; }"
        : "=r"(a) : "l"(p));
    return a;
}
__device__ __forceinline__ void cp16(uint32_t s, const void* g) {
    asm volatile("cp.async.cg.shared.global [%0], [%1], 16;"
                 :: "r"(s), "l"(g) : "memory");
}
__device__ __forceinline__ void cp_commit() {
    asm volatile("cp.async.commit_group;" ::: "memory");
}
template <int N>
__device__ __forceinline__ void cp_wait() {
    asm volatile("cp.async.wait_group %0;" :: "n"(N) : "memory");
}
__device__ __forceinline__ void mma16816(float* d,
                                         uint32_t a0, uint32_t a1,
                                         uint32_t a2, uint32_t a3,
                                         uint32_t b0, uint32_t b1) {
    asm volatile(
        "mma.sync.aligned.m16n8k16.row.col.f32.bf16.bf16.f32 "
        "{%0,%1,%2,%3}, {%4,%5,%6,%7}, {%8,%9}, {%0,%1,%2,%3};"
        : "+f"(d[0]), "+f"(d[1]), "+f"(d[2]), "+f"(d[3])
        : "r"(a0), "r"(a1), "r"(a2), "r"(a3), "r"(b0), "r"(b1));
}
__device__ __forceinline__ float softplusf(float x) {
    return fmaxf(x, 0.0f) + log1pf(expf(-fabsf(x)));
}

// ---------------------------------------------------------------------------
// Kernel 0: convert W and emb to bf16 (rn) once.
// ---------------------------------------------------------------------------
#define NW2 (OUTC * HID / 2)     // 4,030,464 u32
#define NE2 (TOKENS * HID / 2)   //   262,144 u32

__global__ void __launch_bounds__(256) cvt_bf16_kernel(
    const float* __restrict__ W, const float* __restrict__ emb)
{
    const int stride = gridDim.x * blockDim.x;
    uint32_t* wo = (uint32_t*)g_wbf;
    uint32_t* eo = (uint32_t*)g_ebf;
    for (int i = blockIdx.x * blockDim.x + threadIdx.x; i < NW2 + NE2;
         i += stride) {
        if (i < NW2) {
            float2 v = *(const float2*)(W + 2 * (size_t)i);
            wo[i] = pack_bf16(v.x, v.y);
        } else {
            const int j = i - NW2;
            float2 v = *(const float2*)(emb + 2 * (size_t)j);
            eo[j] = pack_bf16(v.x, v.y);
        }
    }
}

// ---------------------------------------------------------------------------
// Stage 1: bf16 tensor-core GEMM + softplus + bf16 store
//   Reads pre-converted bf16 operands via 4-deep cp.async pipeline, BK=32.
//   CTA tile 128(t) x 128(o), 8 warps of 64x32 via m16n8k16.
// ---------------------------------------------------------------------------
#define RS1 20                    // row stride in u32 (16 data + 4 pad)
#define S1_TILE (128 * RS1)       // u32 per operand per stage
#define S1_STG 4
#define SM1_BYTES (2 * S1_STG * S1_TILE * 4)   // 81920

__global__ void __launch_bounds__(256, 2) gemm_softplus_bf16(
    const float* __restrict__ bias)
{
    extern __shared__ uint32_t s1[];
    uint32_t* As = s1;                       // emb tiles [stg][128][RS1]
    uint32_t* Bs = s1 + S1_STG * S1_TILE;    // W tiles

    const int t0 = blockIdx.y * 128;
    const int o0 = blockIdx.x * 128;
    const int tid = threadIdx.x;
    const int wid = tid >> 5, lane = tid & 31;
    const int wm = (wid & 1) * 64;
    const int wn = (wid >> 1) * 32;
    const int r = lane >> 2, qc = lane & 3;

    // Loader: row = tid>>1, two cp16 per operand at u32 cols h4+{0,8}
    const int lrow = tid >> 1;
    const int h4 = (tid & 1) * 4;            // u32 col 0 or 4
    const __nv_bfloat16* eRow = g_ebf + (size_t)(t0 + lrow) * HID + h4 * 2;
    const __nv_bfloat16* wRow = g_wbf + (size_t)(o0 + lrow) * HID + h4 * 2;
    const uint32_t sA = smem_u32(As) + (uint32_t)(lrow * RS1 + h4) * 4u;
    const uint32_t sB = smem_u32(Bs) + (uint32_t)(lrow * RS1 + h4) * 4u;

    float acc[4][4][4];
    #pragma unroll
    for (int mt = 0; mt < 4; mt++)
        #pragma unroll
        for (int nt = 0; nt < 4; nt++)
            #pragma unroll
            for (int q = 0; q < 4; q++) acc[mt][nt][q] = 0.0f;

    // Prologue: stages 0..2 (k-chunks of 32 bf16 = 16 u32/row)
    #pragma unroll
    for (int s = 0; s < 3; s++) {
        const int kb = s * 32;               // bf16 k offset
        const uint32_t so = (uint32_t)(s * S1_TILE) * 4u;
        cp16(sA + so, eRow + kb);
        cp16(sA + so + 32u, eRow + kb + 16); // +8 u32 = +16 bf16
        cp16(sB + so, wRow + kb);
        cp16(sB + so + 32u, wRow + kb + 16);
        cp_commit();
    }

    #pragma unroll 1
    for (int it = 0; it < 8; it++) {
        if (it <= 5) cp_wait<2>();
        else if (it == 6) cp_wait<1>();
        else cp_wait<0>();
        __syncthreads();

        if (it < 5) {
            const int s = (it + 3) & 3;
            const int kb = (it + 3) * 32;
            const uint32_t so = (uint32_t)(s * S1_TILE) * 4u;
            cp16(sA + so, eRow + kb);
            cp16(sA + so + 32u, eRow + kb + 16);
            cp16(sB + so, wRow + kb);
            cp16(sB + so + 32u, wRow + kb + 16);
            cp_commit();
        }

        const uint32_t* Ac = As + (it & 3) * S1_TILE;
        const uint32_t* Bc = Bs + (it & 3) * S1_TILE;
        #pragma unroll
        for (int kk = 0; kk < 2; kk++) {
            const int kb = kk * 8;           // u32 offset of k16 sub-block
            uint32_t a[4][4], b[4][2];
            #pragma unroll
            for (int mt = 0; mt < 4; mt++) {
                const uint32_t* p = &Ac[(wm + mt * 16 + r) * RS1 + kb];
                a[mt][0] = p[qc];
                a[mt][1] = p[8 * RS1 + qc];
                a[mt][2] = p[qc + 4];
                a[mt][3] = p[8 * RS1 + qc + 4];
            }
            #pragma unroll
            for (int nt = 0; nt < 4; nt++) {
                const uint32_t* p = &Bc[(wn + nt * 8 + r) * RS1 + kb];
                b[nt][0] = p[qc];
                b[nt][1] = p[qc + 4];
            }
            #pragma unroll
            for (int mt = 0; mt < 4; mt++)
                #pragma unroll
                for (int nt = 0; nt < 4; nt++)
                    mma16816(acc[mt][nt], a[mt][0], a[mt][1], a[mt][2],
                             a[mt][3], b[nt][0], b[nt][1]);
        }
    }

    // Epilogue: +bias, softplus, pack bf16x2, store token-major
    uint32_t* gb = (uint32_t*)g_bin;
    #pragma unroll
    for (int mt = 0; mt < 4; mt++) {
        const int tA = t0 + wm + mt * 16 + r;
        const size_t row0 = (size_t)tA * (OUTC / 2);
        const size_t row1 = (size_t)(tA + 8) * (OUTC / 2);
        #pragma unroll
        for (int nt = 0; nt < 4; nt++) {
            const int o = o0 + wn + nt * 8 + 2 * qc;
            const float2 bi = *(const float2*)(bias + o);
            float s0 = softplusf(acc[mt][nt][0] + bi.x);
            float s1 = softplusf(acc[mt][nt][1] + bi.y);
            float s2 = softplusf(acc[mt][nt][2] + bi.x);
            float s3 = softplusf(acc[mt][nt][3] + bi.y);
            gb[row0 + (o >> 1)] = pack_bf16(s0, s1);
            gb[row1 + (o >> 1)] = pack_bf16(s2, s3);
        }
    }
}

// ---------------------------------------------------------------------------
// Stage 2: per-token triple contraction (round-9 kernel, unchanged, 437 us)
// ---------------------------------------------------------------------------
#define RS 132
#define EYB 41
#define EZB 89
#define SM2_U32 (137 * RS)
#define SM2_BYTES (SM2_U32 * 4)   // 72336

__device__ __forceinline__ uint32_t bmul2(uint32_t a, uint32_t b) {
    uint32_t d;
    asm("mul.bf16x2 %0, %1, %2;" : "=r"(d) : "r"(a), "r"(b));
    return d;
}

__global__ void __launch_bounds__(256, 2) triple_mma_kernel(
    const float* __restrict__ ls, float* __restrict__ out)
{
    extern __shared__ uint32_t sm[];
    const int tid = threadIdx.x;
    const int wid = tid >> 5;
    const int lid = tid & 31;
    const int rowin = lid >> 2;
    const int qc = lid & 3;
    const int t = blockIdx.x;

    const uint4* src = (const uint4*)(g_bin + (size_t)t * OUTC);
    for (int i = tid; i < CBIN * 32; i += 256) {
        const int cc = i >> 5;
        const int j = i & 31;
        const int dr = cc + (cc >= 82 ? 7 : 0);
        *(uint4*)&sm[dr * RS + j * 4] = src[i];
    }
    for (int i = tid; i < 7 * RS; i += 256) {
        sm[82 * RS + i] = 0u;
        sm[130 * RS + i] = 0u;
    }
    __syncthreads();

    const float scale = expf(ls[0]);
    float* __restrict__ outT = out + (size_t)t * OPT;

    for (int j = wid; j < 63; j += 8) {
        const int zt = j / 21;
        const int xp = j - zt * 21;
        const int x0 = 2 * xp;
        const bool hasx1 = (x0 + 1 < NB);
        const int x1 = hasx1 ? (x0 + 1) : (NB - 1);
        const int z0 = zt * 16;

        float acc[2][6][4];
        #pragma unroll
        for (int xi = 0; xi < 2; xi++)
            #pragma unroll
            for (int g = 0; g < 6; g++)
                #pragma unroll
                for (int qq = 0; qq < 4; qq++) acc[xi][g][qq] = 0.0f;

        const uint32_t* __restrict__ ex0p = sm + x0 * RS;
        const uint32_t* __restrict__ ex1p = sm + x1 * RS;
        const uint32_t* __restrict__ ezA = sm + (EZB + z0 + rowin) * RS;
        const uint32_t* __restrict__ ezB = ezA + 8 * RS;
        const uint32_t* __restrict__ eyp = sm + (EYB + rowin) * RS;

        #pragma unroll
        for (int k = 0; k < 16; k++) {
            const int c0 = k * 8 + qc;
            const int c1 = c0 + 4;
            const uint32_t ez0 = ezA[c0], ez1 = ezB[c0];
            const uint32_t ez2 = ezA[c1], ez3 = ezB[c1];
            const uint32_t exa0 = ex0p[c0], exa1 = ex0p[c1];
            const uint32_t exb0 = ex1p[c0], exb1 = ex1p[c1];
            const uint32_t A00 = bmul2(ez0, exa0), A01 = bmul2(ez1, exa0);
            const uint32_t A02 = bmul2(ez2, exa1), A03 = bmul2(ez3, exa1);
            const uint32_t A10 = bmul2(ez0, exb0), A11 = bmul2(ez1, exb0);
            const uint32_t A12 = bmul2(ez2, exb1), A13 = bmul2(ez3, exb1);
            #pragma unroll
            for (int g = 0; g < 6; g++) {
                const uint32_t b0 = eyp[g * 8 * RS + c0];
                const uint32_t b1 = eyp[g * 8 * RS + c1];
                mma16816(acc[0][g], A00, A01, A02, A03, b0, b1);
                mma16816(acc[1][g], A10, A11, A12, A13, b0, b1);
            }
        }

        const int zlo = z0 + rowin;
        const int zhi = zlo + 8;
        #pragma unroll
        for (int xi = 0; xi < 2; xi++) {
            if (xi == 1 && !hasx1) break;
            const int x = xi ? x1 : x0;
            float* const obase = outT + x * NB;
            #pragma unroll
            for (int g = 0; g < 6; g++) {
                const int y = 8 * g + 2 * qc;
                if (y < NB) {
                    obase[(size_t)y * NXZ + zlo] = acc[xi][g][0] * scale;
                    if (zhi < NB) obase[(size_t)y * NXZ + zhi] = acc[xi][g][2] * scale;
                }
                if (y + 1 < NB) {
                    obase[(size_t)(y + 1) * NXZ + zlo] = acc[xi][g][1] * scale;
                    if (zhi < NB) obase[(size_t)(y + 1) * NXZ + zhi] = acc[xi][g][3] * scale;
                }
            }
        }
    }
}

// ---------------------------------------------------------------------------
// Launch (single stream — overlap attempt reverted)
// ---------------------------------------------------------------------------
extern "C" void kernel_launch(void* const* d_in, const int* in_sizes, int n_in,
                              void* d_out, int out_size)
{
    const float *emb = nullptr, *W = nullptr, *bias = nullptr, *ls = nullptr;
    for (int i = 0; i < n_in; i++) {
        switch (in_sizes[i]) {
            case TOKENS * HID:   emb  = (const float*)d_in[i]; break;
            case OUTC * HID:     W    = (const float*)d_in[i]; break;
            case OUTC:           bias = (const float*)d_in[i]; break;
            case 1:              ls   = (const float*)d_in[i]; break;
            default: break;
        }
    }

    cvt_bf16_kernel<<<2048, 256>>>(W, emb);

    cudaFuncSetAttribute(gemm_softplus_bf16,
                         cudaFuncAttributeMaxDynamicSharedMemorySize,
                         SM1_BYTES);
    dim3 g1(OUTC / 128, TOKENS / 128);  // 246 x 16
    gemm_softplus_bf16<<<g1, 256, SM1_BYTES>>>(bias);

    cudaFuncSetAttribute(triple_mma_kernel,
                         cudaFuncAttributeMaxDynamicSharedMemorySize,
                         SM2_BYTES);
    triple_mma_kernel<<<TOKENS, 256, SM2_BYTES>>>(ls, (float*)d_out);
}

// round 12
// speedup vs baseline: 1.1957x; 1.0085x over previous
#include <cuda_runtime.h>
#include <cuda_bf16.h>
#include <math.h>
#include <stdint.h>

// Problem constants
#define TOKENS 2048
#define HID 256
#define NB 41
#define CBIN 123
#define OUTC (CBIN * HID)    // 31488
#define OPT (NB * NB * NB)   // 68921
#define NXZ (NB * NB)        // 1681

// Scratch
__device__ __nv_bfloat16 g_bin[(size_t)TOKENS * OUTC];   // stage-1 output
__device__ __nv_bfloat16 g_wbf[(size_t)OUTC * HID];      // W in bf16
__device__ __nv_bfloat16 g_ebf[(size_t)TOKENS * HID];    // emb in bf16

// ---------------------------------------------------------------------------
// Helpers
// ---------------------------------------------------------------------------
__device__ __forceinline__ uint32_t pack_bf16(float a, float b) {
    __nv_bfloat162 t = __float22bfloat162_rn(make_float2(a, b));
    return *(uint32_t*)&t;
}
__device__ __forceinline__ uint32_t smem_u32(const void* p) {
    uint32_t a;
    asm("{ .reg .u64 t; cvta.to.shared.u64 t, %1; cvt.u32.u64 %0, t; }"
        : "=r"(a) : "l"(p));
    return a;
}
__device__ __forceinline__ void cp16(uint32_t s, const void* g) {
    asm volatile("cp.async.cg.shared.global [%0], [%1], 16;"
                 :: "r"(s), "l"(g) : "memory");
}
__device__ __forceinline__ void cp_commit() {
    asm volatile("cp.async.commit_group;" ::: "memory");
}
template <int N>
__device__ __forceinline__ void cp_wait() {
    asm volatile("cp.async.wait_group %0;" :: "n"(N) : "memory");
}
__device__ __forceinline__ void ldsm_x4(uint32_t* r, uint32_t addr) {
    asm volatile(
        "ldmatrix.sync.aligned.m8n8.x4.shared.b16 {%0,%1,%2,%3}, [%4];"
        : "=r"(r[0]), "=r"(r[1]), "=r"(r[2]), "=r"(r[3]) : "r"(addr));
}
__device__ __forceinline__ void mma16816(float* d,
                                         uint32_t a0, uint32_t a1,
                                         uint32_t a2, uint32_t a3,
                                         uint32_t b0, uint32_t b1) {
    asm volatile(
        "mma.sync.aligned.m16n8k16.row.col.f32.bf16.bf16.f32 "
        "{%0,%1,%2,%3}, {%4,%5,%6,%7}, {%8,%9}, {%0,%1,%2,%3};"
        : "+f"(d[0]), "+f"(d[1]), "+f"(d[2]), "+f"(d[3])
        : "r"(a0), "r"(a1), "r"(a2), "r"(a3), "r"(b0), "r"(b1));
}
__device__ __forceinline__ float softplusf(float x) {
    return fmaxf(x, 0.0f) + log1pf(expf(-fabsf(x)));
}

// ---------------------------------------------------------------------------
// Kernel 0: convert W and emb to bf16 (rn) once. (13.4 us measured)
// ---------------------------------------------------------------------------
#define NW2 (OUTC * HID / 2)
#define NE2 (TOKENS * HID / 2)

__global__ void __launch_bounds__(256) cvt_bf16_kernel(
    const float* __restrict__ W, const float* __restrict__ emb)
{
    const int stride = gridDim.x * blockDim.x;
    uint32_t* wo = (uint32_t*)g_wbf;
    uint32_t* eo = (uint32_t*)g_ebf;
    for (int i = blockIdx.x * blockDim.x + threadIdx.x; i < NW2 + NE2;
         i += stride) {
        if (i < NW2) {
            float2 v = *(const float2*)(W + 2 * (size_t)i);
            wo[i] = pack_bf16(v.x, v.y);
        } else {
            const int j = i - NW2;
            float2 v = *(const float2*)(emb + 2 * (size_t)j);
            eo[j] = pack_bf16(v.x, v.y);
        }
    }
}

// ---------------------------------------------------------------------------
// Stage 1: bf16 GEMM + softplus + bf16 store.
//   cp.async 4-stage, BK=32, fragments via ldmatrix.x4 (6 loads per k16).
// ---------------------------------------------------------------------------
#define RS1 20                    // row stride in u32 (16 data + 4 pad)
#define S1_TILE (128 * RS1)       // u32 per operand per stage
#define S1_STG 4
#define SM1_BYTES (2 * S1_STG * S1_TILE * 4)   // 81920

__global__ void __launch_bounds__(256, 2) gemm_softplus_bf16(
    const float* __restrict__ bias)
{
    extern __shared__ uint32_t s1[];
    uint32_t* As = s1;
    uint32_t* Bs = s1 + S1_STG * S1_TILE;

    const int t0 = blockIdx.y * 128;
    const int o0 = blockIdx.x * 128;
    const int tid = threadIdx.x;
    const int wid = tid >> 5, lane = tid & 31;
    const int wm = (wid & 1) * 64;
    const int wn = (wid >> 1) * 32;
    const int r = lane >> 2, qc = lane & 3;

    // Loader: row = tid>>1, two cp16 per operand
    const int lrow = tid >> 1;
    const int h4 = (tid & 1) * 4;
    const __nv_bfloat16* eRow = g_ebf + (size_t)(t0 + lrow) * HID + h4 * 2;
    const __nv_bfloat16* wRow = g_wbf + (size_t)(o0 + lrow) * HID + h4 * 2;
    const uint32_t sA = smem_u32(As) + (uint32_t)(lrow * RS1 + h4) * 4u;
    const uint32_t sB = smem_u32(Bs) + (uint32_t)(lrow * RS1 + h4) * 4u;

    // ldmatrix per-lane byte offsets within a stage tile
    const uint32_t laneA = (uint32_t)((wm + (lane & 15)) * RS1 +
                                      ((lane >> 4) << 2)) * 4u;
    const uint32_t laneB = (uint32_t)((wn + (lane & 7) + ((lane >> 4) << 3)) * RS1 +
                                      (((lane >> 3) & 1) << 2)) * 4u;
    const uint32_t Abase = smem_u32(As);
    const uint32_t Bbase = smem_u32(Bs);

    float acc[4][4][4];
    #pragma unroll
    for (int mt = 0; mt < 4; mt++)
        #pragma unroll
        for (int nt = 0; nt < 4; nt++)
            #pragma unroll
            for (int q = 0; q < 4; q++) acc[mt][nt][q] = 0.0f;

    // Prologue: stages 0..2
    #pragma unroll
    for (int s = 0; s < 3; s++) {
        const int kb = s * 32;
        const uint32_t so = (uint32_t)(s * S1_TILE) * 4u;
        cp16(sA + so, eRow + kb);
        cp16(sA + so + 32u, eRow + kb + 16);
        cp16(sB + so, wRow + kb);
        cp16(sB + so + 32u, wRow + kb + 16);
        cp_commit();
    }

    #pragma unroll 1
    for (int it = 0; it < 8; it++) {
        if (it <= 5) cp_wait<2>();
        else if (it == 6) cp_wait<1>();
        else cp_wait<0>();
        __syncthreads();

        if (it < 5) {
            const int s = (it + 3) & 3;
            const int kb = (it + 3) * 32;
            const uint32_t so = (uint32_t)(s * S1_TILE) * 4u;
            cp16(sA + so, eRow + kb);
            cp16(sA + so + 32u, eRow + kb + 16);
            cp16(sB + so, wRow + kb);
            cp16(sB + so + 32u, wRow + kb + 16);
            cp_commit();
        }

        const uint32_t stg = (uint32_t)((it & 3) * S1_TILE) * 4u;
        #pragma unroll
        for (int kk = 0; kk < 2; kk++) {
            const uint32_t kbo = (uint32_t)kk * 32u;   // 8 u32
            uint32_t a[4][4], b[2][4];
            #pragma unroll
            for (int mt = 0; mt < 4; mt++)
                ldsm_x4(a[mt], Abase + stg + laneA +
                               (uint32_t)(mt * 16 * RS1) * 4u + kbo);
            #pragma unroll
            for (int j = 0; j < 2; j++)
                ldsm_x4(b[j], Bbase + stg + laneB +
                              (uint32_t)(j * 16 * RS1) * 4u + kbo);
            #pragma unroll
            for (int mt = 0; mt < 4; mt++) {
                mma16816(acc[mt][0], a[mt][0], a[mt][1], a[mt][2], a[mt][3],
                         b[0][0], b[0][1]);
                mma16816(acc[mt][1], a[mt][0], a[mt][1], a[mt][2], a[mt][3],
                         b[0][2], b[0][3]);
                mma16816(acc[mt][2], a[mt][0], a[mt][1], a[mt][2], a[mt][3],
                         b[1][0], b[1][1]);
                mma16816(acc[mt][3], a[mt][0], a[mt][1], a[mt][2], a[mt][3],
                         b[1][2], b[1][3]);
            }
        }
    }

    // Epilogue: +bias, softplus, pack bf16x2, store token-major
    uint32_t* gb = (uint32_t*)g_bin;
    #pragma unroll
    for (int mt = 0; mt < 4; mt++) {
        const int tA = t0 + wm + mt * 16 + r;
        const size_t row0 = (size_t)tA * (OUTC / 2);
        const size_t row1 = (size_t)(tA + 8) * (OUTC / 2);
        #pragma unroll
        for (int nt = 0; nt < 4; nt++) {
            const int o = o0 + wn + nt * 8 + 2 * qc;
            const float2 bi = *(const float2*)(bias + o);
            float s0 = softplusf(acc[mt][nt][0] + bi.x);
            float s1 = softplusf(acc[mt][nt][1] + bi.y);
            float s2 = softplusf(acc[mt][nt][2] + bi.x);
            float s3 = softplusf(acc[mt][nt][3] + bi.y);
            gb[row0 + (o >> 1)] = pack_bf16(s0, s1);
            gb[row1 + (o >> 1)] = pack_bf16(s2, s3);
        }
    }
}

// ---------------------------------------------------------------------------
// Stage 2: per-token triple contraction (unchanged, 437 us, at mma.sync cap)
// ---------------------------------------------------------------------------
#define RS 132
#define EYB 41
#define EZB 89
#define SM2_U32 (137 * RS)
#define SM2_BYTES (SM2_U32 * 4)   // 72336

__device__ __forceinline__ uint32_t bmul2(uint32_t a, uint32_t b) {
    uint32_t d;
    asm("mul.bf16x2 %0, %1, %2;" : "=r"(d) : "r"(a), "r"(b));
    return d;
}

__global__ void __launch_bounds__(256, 2) triple_mma_kernel(
    const float* __restrict__ ls, float* __restrict__ out)
{
    extern __shared__ uint32_t sm[];
    const int tid = threadIdx.x;
    const int wid = tid >> 5;
    const int lid = tid & 31;
    const int rowin = lid >> 2;
    const int qc = lid & 3;
    const int t = blockIdx.x;

    const uint4* src = (const uint4*)(g_bin + (size_t)t * OUTC);
    for (int i = tid; i < CBIN * 32; i += 256) {
        const int cc = i >> 5;
        const int j = i & 31;
        const int dr = cc + (cc >= 82 ? 7 : 0);
        *(uint4*)&sm[dr * RS + j * 4] = src[i];
    }
    for (int i = tid; i < 7 * RS; i += 256) {
        sm[82 * RS + i] = 0u;
        sm[130 * RS + i] = 0u;
    }
    __syncthreads();

    const float scale = expf(ls[0]);
    float* __restrict__ outT = out + (size_t)t * OPT;

    for (int j = wid; j < 63; j += 8) {
        const int zt = j / 21;
        const int xp = j - zt * 21;
        const int x0 = 2 * xp;
        const bool hasx1 = (x0 + 1 < NB);
        const int x1 = hasx1 ? (x0 + 1) : (NB - 1);
        const int z0 = zt * 16;

        float acc[2][6][4];
        #pragma unroll
        for (int xi = 0; xi < 2; xi++)
            #pragma unroll
            for (int g = 0; g < 6; g++)
                #pragma unroll
                for (int qq = 0; qq < 4; qq++) acc[xi][g][qq] = 0.0f;

        const uint32_t* __restrict__ ex0p = sm + x0 * RS;
        const uint32_t* __restrict__ ex1p = sm + x1 * RS;
        const uint32_t* __restrict__ ezA = sm + (EZB + z0 + rowin) * RS;
        const uint32_t* __restrict__ ezB = ezA + 8 * RS;
        const uint32_t* __restrict__ eyp = sm + (EYB + rowin) * RS;

        #pragma unroll
        for (int k = 0; k < 16; k++) {
            const int c0 = k * 8 + qc;
            const int c1 = c0 + 4;
            const uint32_t ez0 = ezA[c0], ez1 = ezB[c0];
            const uint32_t ez2 = ezA[c1], ez3 = ezB[c1];
            const uint32_t exa0 = ex0p[c0], exa1 = ex0p[c1];
            const uint32_t exb0 = ex1p[c0], exb1 = ex1p[c1];
            const uint32_t A00 = bmul2(ez0, exa0), A01 = bmul2(ez1, exa0);
            const uint32_t A02 = bmul2(ez2, exa1), A03 = bmul2(ez3, exa1);
            const uint32_t A10 = bmul2(ez0, exb0), A11 = bmul2(ez1, exb0);
            const uint32_t A12 = bmul2(ez2, exb1), A13 = bmul2(ez3, exb1);
            #pragma unroll
            for (int g = 0; g < 6; g++) {
                const uint32_t b0 = eyp[g * 8 * RS + c0];
                const uint32_t b1 = eyp[g * 8 * RS + c1];
                mma16816(acc[0][g], A00, A01, A02, A03, b0, b1);
                mma16816(acc[1][g], A10, A11, A12, A13, b0, b1);
            }
        }

        const int zlo = z0 + rowin;
        const int zhi = zlo + 8;
        #pragma unroll
        for (int xi = 0; xi < 2; xi++) {
            if (xi == 1 && !hasx1) break;
            const int x = xi ? x1 : x0;
            float* const obase = outT + x * NB;
            #pragma unroll
            for (int g = 0; g < 6; g++) {
                const int y = 8 * g + 2 * qc;
                if (y < NB) {
                    obase[(size_t)y * NXZ + zlo] = acc[xi][g][0] * scale;
                    if (zhi < NB) obase[(size_t)y * NXZ + zhi] = acc[xi][g][2] * scale;
                }
                if (y + 1 < NB) {
                    obase[(size_t)(y + 1) * NXZ + zlo] = acc[xi][g][1] * scale;
                    if (zhi < NB) obase[(size_t)(y + 1) * NXZ + zhi] = acc[xi][g][3] * scale;
                }
            }
        }
    }
}

// ---------------------------------------------------------------------------
// Launch
// ---------------------------------------------------------------------------
extern "C" void kernel_launch(void* const* d_in, const int* in_sizes, int n_in,
                              void* d_out, int out_size)
{
    const float *emb = nullptr, *W = nullptr, *bias = nullptr, *ls = nullptr;
    for (int i = 0; i < n_in; i++) {
        switch (in_sizes[i]) {
            case TOKENS * HID:   emb  = (const float*)d_in[i]; break;
            case OUTC * HID:     W    = (const float*)d_in[i]; break;
            case OUTC:           bias = (const float*)d_in[i]; break;
            case 1:              ls   = (const float*)d_in[i]; break;
            default: break;
        }
    }

    cvt_bf16_kernel<<<2048, 256>>>(W, emb);

    cudaFuncSetAttribute(gemm_softplus_bf16,
                         cudaFuncAttributeMaxDynamicSharedMemorySize,
                         SM1_BYTES);
    dim3 g1(OUTC / 128, TOKENS / 128);  // 246 x 16
    gemm_softplus_bf16<<<g1, 256, SM1_BYTES>>>(bias);

    cudaFuncSetAttribute(triple_mma_kernel,
                         cudaFuncAttributeMaxDynamicSharedMemorySize,
                         SM2_BYTES);
    triple_mma_kernel<<<TOKENS, 256, SM2_BYTES>>>(ls, (float*)d_out);
}

// round 14
// speedup vs baseline: 1.2813x; 1.0716x over previous
#include <cuda_runtime.h>
#include <cuda_bf16.h>
#include <math.h>
#include <stdint.h>

// Problem constants
#define TOKENS 2048
#define HID 256
#define NB 41
#define CBIN 123
#define OUTC (CBIN * HID)    // 31488
#define OPT (NB * NB * NB)   // 68921
#define NXZ (NB * NB)        // 1681

// Scratch
__device__ __nv_bfloat16 g_bin[(size_t)TOKENS * OUTC];
__device__ __nv_bfloat16 g_wbf[(size_t)OUTC * HID];
__device__ __nv_bfloat16 g_ebf[(size_t)TOKENS * HID];

// ---------------------------------------------------------------------------
// Helpers
// ---------------------------------------------------------------------------
__device__ __forceinline__ uint32_t pack_bf16(float a, float b) {
    __nv_bfloat162 t = __float22bfloat162_rn(make_float2(a, b));
    return *(uint32_t*)&t;
}
__device__ __forceinline__ uint32_t smem_u32(const void* p) {
    uint32_t a;
    asm("{ .reg .u64 t; cvta.to.shared.u64 t, %1; cvt.u32.u64 %0, t; }"
        : "=r"(a) : "l"(p));
    return a;
}
__device__ __forceinline__ void cp16(uint32_t s, const void* g) {
    asm volatile("cp.async.cg.shared.global [%0], [%1], 16;"
                 :: "r"(s), "l"(g) : "memory");
}
__device__ __forceinline__ void cp_commit() {
    asm volatile("cp.async.commit_group;" ::: "memory");
}
template <int N>
__device__ __forceinline__ void cp_wait() {
    asm volatile("cp.async.wait_group %0;" :: "n"(N) : "memory");
}
__device__ __forceinline__ void ldsm_x4(uint32_t* r, uint32_t addr) {
    asm volatile(
        "ldmatrix.sync.aligned.m8n8.x4.shared.b16 {%0,%1,%2,%3}, [%4];"
        : "=r"(r[0]), "=r"(r[1]), "=r"(r[2]), "=r"(r[3]) : "r"(addr));
}
__device__ __forceinline__ void mma16816(float* d,
                                         uint32_t a0, uint32_t a1,
                                         uint32_t a2, uint32_t a3,
                                         uint32_t b0, uint32_t b1) {
    asm volatile(
        "mma.sync.aligned.m16n8k16.row.col.f32.bf16.bf16.f32 "
        "{%0,%1,%2,%3}, {%4,%5,%6,%7}, {%8,%9}, {%0,%1,%2,%3};"
        : "+f"(d[0]), "+f"(d[1]), "+f"(d[2]), "+f"(d[3])
        : "r"(a0), "r"(a1), "r"(a2), "r"(a3), "r"(b0), "r"(b1));
}
// Fast softplus: __expf/__logf intrinsics (MUFU); abs err ~1e-6 << bf16 noise
__device__ __forceinline__ float softplusf(float x) {
    return fmaxf(x, 0.0f) + __logf(1.0f + __expf(-fabsf(x)));
}

// ---------------------------------------------------------------------------
// Kernel 0: convert W and emb to bf16 (rn) once. (~13 us)
// ---------------------------------------------------------------------------
#define NW2 (OUTC * HID / 2)
#define NE2 (TOKENS * HID / 2)

__global__ void __launch_bounds__(256) cvt_bf16_kernel(
    const float* __restrict__ W, const float* __restrict__ emb)
{
    const int stride = gridDim.x * blockDim.x;
    uint32_t* wo = (uint32_t*)g_wbf;
    uint32_t* eo = (uint32_t*)g_ebf;
    for (int i = blockIdx.x * blockDim.x + threadIdx.x; i < NW2 + NE2;
         i += stride) {
        if (i < NW2) {
            float2 v = *(const float2*)(W + 2 * (size_t)i);
            wo[i] = pack_bf16(v.x, v.y);
        } else {
            const int j = i - NW2;
            float2 v = *(const float2*)(emb + 2 * (size_t)j);
            eo[j] = pack_bf16(v.x, v.y);
        }
    }
}

// ---------------------------------------------------------------------------
// Stage 1: bf16 GEMM + softplus + bf16 store (cp.async 4-stage, ldmatrix)
// ---------------------------------------------------------------------------
#define RS1 20
#define S1_TILE (128 * RS1)
#define S1_STG 4
#define SM1_BYTES (2 * S1_STG * S1_TILE * 4)   // 81920

__global__ void __launch_bounds__(256, 2) gemm_softplus_bf16(
    const float* __restrict__ bias)
{
    extern __shared__ uint32_t s1[];
    uint32_t* As = s1;
    uint32_t* Bs = s1 + S1_STG * S1_TILE;

    const int t0 = blockIdx.y * 128;
    const int o0 = blockIdx.x * 128;
    const int tid = threadIdx.x;
    const int wid = tid >> 5, lane = tid & 31;
    const int wm = (wid & 1) * 64;
    const int wn = (wid >> 1) * 32;
    const int r = lane >> 2, qc = lane & 3;

    const int lrow = tid >> 1;
    const int h4 = (tid & 1) * 4;
    const __nv_bfloat16* eRow = g_ebf + (size_t)(t0 + lrow) * HID + h4 * 2;
    const __nv_bfloat16* wRow = g_wbf + (size_t)(o0 + lrow) * HID + h4 * 2;
    const uint32_t sA = smem_u32(As) + (uint32_t)(lrow * RS1 + h4) * 4u;
    const uint32_t sB = smem_u32(Bs) + (uint32_t)(lrow * RS1 + h4) * 4u;

    const uint32_t laneA = (uint32_t)((wm + (lane & 15)) * RS1 +
                                      ((lane >> 4) << 2)) * 4u;
    const uint32_t laneB = (uint32_t)((wn + (lane & 7) + ((lane >> 4) << 3)) * RS1 +
                                      (((lane >> 3) & 1) << 2)) * 4u;
    const uint32_t Abase = smem_u32(As);
    const uint32_t Bbase = smem_u32(Bs);

    float acc[4][4][4];
    #pragma unroll
    for (int mt = 0; mt < 4; mt++)
        #pragma unroll
        for (int nt = 0; nt < 4; nt++)
            #pragma unroll
            for (int q = 0; q < 4; q++) acc[mt][nt][q] = 0.0f;

    #pragma unroll
    for (int s = 0; s < 3; s++) {
        const int kb = s * 32;
        const uint32_t so = (uint32_t)(s * S1_TILE) * 4u;
        cp16(sA + so, eRow + kb);
        cp16(sA + so + 32u, eRow + kb + 16);
        cp16(sB + so, wRow + kb);
        cp16(sB + so + 32u, wRow + kb + 16);
        cp_commit();
    }

    #pragma unroll 1
    for (int it = 0; it < 8; it++) {
        if (it <= 5) cp_wait<2>();
        else if (it == 6) cp_wait<1>();
        else cp_wait<0>();
        __syncthreads();

        if (it < 5) {
            const int s = (it + 3) & 3;
            const int kb = (it + 3) * 32;
            const uint32_t so = (uint32_t)(s * S1_TILE) * 4u;
            cp16(sA + so, eRow + kb);
            cp16(sA + so + 32u, eRow + kb + 16);
            cp16(sB + so, wRow + kb);
            cp16(sB + so + 32u, wRow + kb + 16);
            cp_commit();
        }

        const uint32_t stg = (uint32_t)((it & 3) * S1_TILE) * 4u;
        #pragma unroll
        for (int kk = 0; kk < 2; kk++) {
            const uint32_t kbo = (uint32_t)kk * 32u;
            uint32_t a[4][4], b[2][4];
            #pragma unroll
            for (int mt = 0; mt < 4; mt++)
                ldsm_x4(a[mt], Abase + stg + laneA +
                               (uint32_t)(mt * 16 * RS1) * 4u + kbo);
            #pragma unroll
            for (int j = 0; j < 2; j++)
                ldsm_x4(b[j], Bbase + stg + laneB +
                              (uint32_t)(j * 16 * RS1) * 4u + kbo);
            #pragma unroll
            for (int mt = 0; mt < 4; mt++) {
                mma16816(acc[mt][0], a[mt][0], a[mt][1], a[mt][2], a[mt][3],
                         b[0][0], b[0][1]);
                mma16816(acc[mt][1], a[mt][0], a[mt][1], a[mt][2], a[mt][3],
                         b[0][2], b[0][3]);
                mma16816(acc[mt][2], a[mt][0], a[mt][1], a[mt][2], a[mt][3],
                         b[1][0], b[1][1]);
                mma16816(acc[mt][3], a[mt][0], a[mt][1], a[mt][2], a[mt][3],
                         b[1][2], b[1][3]);
            }
        }
    }

    uint32_t* gb = (uint32_t*)g_bin;
    #pragma unroll
    for (int mt = 0; mt < 4; mt++) {
        const int tA = t0 + wm + mt * 16 + r;
        const size_t row0 = (size_t)tA * (OUTC / 2);
        const size_t row1 = (size_t)(tA + 8) * (OUTC / 2);
        #pragma unroll
        for (int nt = 0; nt < 4; nt++) {
            const int o = o0 + wn + nt * 8 + 2 * qc;
            const float2 bi = *(const float2*)(bias + o);
            float s0 = softplusf(acc[mt][nt][0] + bi.x);
            float s1 = softplusf(acc[mt][nt][1] + bi.y);
            float s2 = softplusf(acc[mt][nt][2] + bi.x);
            float s3 = softplusf(acc[mt][nt][3] + bi.y);
            gb[row0 + (o >> 1)] = pack_bf16(s0, s1);
            gb[row1 + (o >> 1)] = pack_bf16(s2, s3);
        }
    }
}

// ---------------------------------------------------------------------------
// Stage 2: per-token triple contraction (at mma.sync cap, unchanged)
// ---------------------------------------------------------------------------
#define RS 132
#define EYB 41
#define EZB 89
#define SM2_U32 (137 * RS)
#define SM2_BYTES (SM2_U32 * 4)   // 72336

__device__ __forceinline__ uint32_t bmul2(uint32_t a, uint32_t b) {
    uint32_t d;
    asm("mul.bf16x2 %0, %1, %2;" : "=r"(d) : "r"(a), "r"(b));
    return d;
}

__global__ void __launch_bounds__(256, 2) triple_mma_kernel(
    const float* __restrict__ ls, float* __restrict__ out)
{
    extern __shared__ uint32_t sm[];
    const int tid = threadIdx.x;
    const int wid = tid >> 5;
    const int lid = tid & 31;
    const int rowin = lid >> 2;
    const int qc = lid & 3;
    const int t = blockIdx.x;

    const uint4* src = (const uint4*)(g_bin + (size_t)t * OUTC);
    for (int i = tid; i < CBIN * 32; i += 256) {
        const int cc = i >> 5;
        const int j = i & 31;
        const int dr = cc + (cc >= 82 ? 7 : 0);
        *(uint4*)&sm[dr * RS + j * 4] = src[i];
    }
    for (int i = tid; i < 7 * RS; i += 256) {
        sm[82 * RS + i] = 0u;
        sm[130 * RS + i] = 0u;
    }
    __syncthreads();

    const float scale = __expf(ls[0]);
    float* __restrict__ outT = out + (size_t)t * OPT;

    for (int j = wid; j < 63; j += 8) {
        const int zt = j / 21;
        const int xp = j - zt * 21;
        const int x0 = 2 * xp;
        const bool hasx1 = (x0 + 1 < NB);
        const int x1 = hasx1 ? (x0 + 1) : (NB - 1);
        const int z0 = zt * 16;

        float acc[2][6][4];
        #pragma unroll
        for (int xi = 0; xi < 2; xi++)
            #pragma unroll
            for (int g = 0; g < 6; g++)
                #pragma unroll
                for (int qq = 0; qq < 4; qq++) acc[xi][g][qq] = 0.0f;

        const uint32_t* __restrict__ ex0p = sm + x0 * RS;
        const uint32_t* __restrict__ ex1p = sm + x1 * RS;
        const uint32_t* __restrict__ ezA = sm + (EZB + z0 + rowin) * RS;
        const uint32_t* __restrict__ ezB = ezA + 8 * RS;
        const uint32_t* __restrict__ eyp = sm + (EYB + rowin) * RS;

        #pragma unroll
        for (int k = 0; k < 16; k++) {
            const int c0 = k * 8 + qc;
            const int c1 = c0 + 4;
            const uint32_t ez0 = ezA[c0], ez1 = ezB[c0];
            const uint32_t ez2 = ezA[c1], ez3 = ezB[c1];
            const uint32_t exa0 = ex0p[c0], exa1 = ex0p[c1];
            const uint32_t exb0 = ex1p[c0], exb1 = ex1p[c1];
            const uint32_t A00 = bmul2(ez0, exa0), A01 = bmul2(ez1, exa0);
            const uint32_t A02 = bmul2(ez2, exa1), A03 = bmul2(ez3, exa1);
            const uint32_t A10 = bmul2(ez0, exb0), A11 = bmul2(ez1, exb0);
            const uint32_t A12 = bmul2(ez2, exb1), A13 = bmul2(ez3, exb1);
            #pragma unroll
            for (int g = 0; g < 6; g++) {
                const uint32_t b0 = eyp[g * 8 * RS + c0];
                const uint32_t b1 = eyp[g * 8 * RS + c1];
                mma16816(acc[0][g], A00, A01, A02, A03, b0, b1);
                mma16816(acc[1][g], A10, A11, A12, A13, b0, b1);
            }
        }

        const int zlo = z0 + rowin;
        const int zhi = zlo + 8;
        #pragma unroll
        for (int xi = 0; xi < 2; xi++) {
            if (xi == 1 && !hasx1) break;
            const int x = xi ? x1 : x0;
            float* const obase = outT + x * NB;
            #pragma unroll
            for (int g = 0; g < 6; g++) {
                const int y = 8 * g + 2 * qc;
                if (y < NB) {
                    obase[(size_t)y * NXZ + zlo] = acc[xi][g][0] * scale;
                    if (zhi < NB) obase[(size_t)y * NXZ + zhi] = acc[xi][g][2] * scale;
                }
                if (y + 1 < NB) {
                    obase[(size_t)(y + 1) * NXZ + zlo] = acc[xi][g][1] * scale;
                    if (zhi < NB) obase[(size_t)(y + 1) * NXZ + zhi] = acc[xi][g][3] * scale;
                }
            }
        }
    }
}

// ---------------------------------------------------------------------------
// Launch (single stream — no extra streams/events: teardown-clean)
// ---------------------------------------------------------------------------
extern "C" void kernel_launch(void* const* d_in, const int* in_sizes, int n_in,
                              void* d_out, int out_size)
{
    const float *emb = nullptr, *W = nullptr, *bias = nullptr, *ls = nullptr;
    for (int i = 0; i < n_in; i++) {
        switch (in_sizes[i]) {
            case TOKENS * HID:   emb  = (const float*)d_in[i]; break;
            case OUTC * HID:     W    = (const float*)d_in[i]; break;
            case OUTC:           bias = (const float*)d_in[i]; break;
            case 1:              ls   = (const float*)d_in[i]; break;
            default: break;
        }
    }

    cvt_bf16_kernel<<<2048, 256>>>(W, emb);

    cudaFuncSetAttribute(gemm_softplus_bf16,
                         cudaFuncAttributeMaxDynamicSharedMemorySize,
                         SM1_BYTES);
    dim3 g1(OUTC / 128, TOKENS / 128);  // 246 x 16
    gemm_softplus_bf16<<<g1, 256, SM1_BYTES>>>(bias);

    cudaFuncSetAttribute(triple_mma_kernel,
                         cudaFuncAttributeMaxDynamicSharedMemorySize,
                         SM2_BYTES);
    triple_mma_kernel<<<TOKENS, 256, SM2_BYTES>>>(ls, (float*)d_out);
}

// round 15
// speedup vs baseline: 1.6148x; 1.2604x over previous
#include <cuda_runtime.h>
#include <cuda_bf16.h>
#include <math.h>
#include <stdint.h>

// Problem constants
#define TOKENS 2048
#define HID 256
#define NB 41
#define CBIN 123
#define OUTC (CBIN * HID)    // 31488
#define OPT (NB * NB * NB)   // 68921
#define NXZ (NB * NB)        // 1681

// Scratch
__device__ __nv_bfloat16 g_bin[(size_t)TOKENS * OUTC];
__device__ __nv_bfloat16 g_wbf[(size_t)OUTC * HID];
__device__ __nv_bfloat16 g_ebf[(size_t)TOKENS * HID];

// ---------------------------------------------------------------------------
// Helpers
// ---------------------------------------------------------------------------
__device__ __forceinline__ uint32_t pack_bf16(float a, float b) {
    __nv_bfloat162 t = __float22bfloat162_rn(make_float2(a, b));
    return *(uint32_t*)&t;
}
__device__ __forceinline__ uint32_t smem_u32(const void* p) {
    uint32_t a;
    asm("{ .reg .u64 t; cvta.to.shared.u64 t, %1; cvt.u32.u64 %0, t; }"
        : "=r"(a) : "l"(p));
    return a;
}
__device__ __forceinline__ void cp16(uint32_t s, const void* g) {
    asm volatile("cp.async.cg.shared.global [%0], [%1], 16;"
                 :: "r"(s), "l"(g) : "memory");
}
__device__ __forceinline__ void cp_commit() {
    asm volatile("cp.async.commit_group;" ::: "memory");
}
template <int N>
__device__ __forceinline__ void cp_wait() {
    asm volatile("cp.async.wait_group %0;" :: "n"(N) : "memory");
}
__device__ __forceinline__ void ldsm_x4(uint32_t* r, uint32_t addr) {
    asm volatile(
        "ldmatrix.sync.aligned.m8n8.x4.shared.b16 {%0,%1,%2,%3}, [%4];"
        : "=r"(r[0]), "=r"(r[1]), "=r"(r[2]), "=r"(r[3]) : "r"(addr));
}
__device__ __forceinline__ void mma16816(float* d,
                                         uint32_t a0, uint32_t a1,
                                         uint32_t a2, uint32_t a3,
                                         uint32_t b0, uint32_t b1) {
    asm volatile(
        "mma.sync.aligned.m16n8k16.row.col.f32.bf16.bf16.f32 "
        "{%0,%1,%2,%3}, {%4,%5,%6,%7}, {%8,%9}, {%0,%1,%2,%3};"
        : "+f"(d[0]), "+f"(d[1]), "+f"(d[2]), "+f"(d[3])
        : "r"(a0), "r"(a1), "r"(a2), "r"(a3), "r"(b0), "r"(b1));
}
// Fast softplus: __expf/__logf intrinsics (MUFU); abs err ~1e-6 << bf16 noise
__device__ __forceinline__ float softplusf(float x) {
    return fmaxf(x, 0.0f) + __logf(1.0f + __expf(-fabsf(x)));
}
__device__ __forceinline__ uint32_t bmul2(uint32_t a, uint32_t b) {
    uint32_t d;
    asm("mul.bf16x2 %0, %1, %2;" : "=r"(d) : "r"(a), "r"(b));
    return d;
}

// ---------------------------------------------------------------------------
// Kernel 0: convert W and emb to bf16 (rn) once. (~13 us)
// ---------------------------------------------------------------------------
#define NW2 (OUTC * HID / 2)
#define NE2 (TOKENS * HID / 2)

__global__ void __launch_bounds__(256) cvt_bf16_kernel(
    const float* __restrict__ W, const float* __restrict__ emb)
{
    const int stride = gridDim.x * blockDim.x;
    uint32_t* wo = (uint32_t*)g_wbf;
    uint32_t* eo = (uint32_t*)g_ebf;
    for (int i = blockIdx.x * blockDim.x + threadIdx.x; i < NW2 + NE2;
         i += stride) {
        if (i < NW2) {
            float2 v = *(const float2*)(W + 2 * (size_t)i);
            wo[i] = pack_bf16(v.x, v.y);
        } else {
            const int j = i - NW2;
            float2 v = *(const float2*)(emb + 2 * (size_t)j);
            eo[j] = pack_bf16(v.x, v.y);
        }
    }
}

// ---------------------------------------------------------------------------
// Stage 1: bf16 GEMM + softplus + bf16 store (unchanged, ~192 us)
// ---------------------------------------------------------------------------
#define RS1 20
#define S1_TILE (128 * RS1)
#define S1_STG 4
#define SM1_BYTES (2 * S1_STG * S1_TILE * 4)   // 81920

__global__ void __launch_bounds__(256, 2) gemm_softplus_bf16(
    const float* __restrict__ bias)
{
    extern __shared__ uint32_t s1[];
    uint32_t* As = s1;
    uint32_t* Bs = s1 + S1_STG * S1_TILE;

    const int t0 = blockIdx.y * 128;
    const int o0 = blockIdx.x * 128;
    const int tid = threadIdx.x;
    const int wid = tid >> 5, lane = tid & 31;
    const int wm = (wid & 1) * 64;
    const int wn = (wid >> 1) * 32;
    const int r = lane >> 2, qc = lane & 3;

    const int lrow = tid >> 1;
    const int h4 = (tid & 1) * 4;
    const __nv_bfloat16* eRow = g_ebf + (size_t)(t0 + lrow) * HID + h4 * 2;
    const __nv_bfloat16* wRow = g_wbf + (size_t)(o0 + lrow) * HID + h4 * 2;
    const uint32_t sA = smem_u32(As) + (uint32_t)(lrow * RS1 + h4) * 4u;
    const uint32_t sB = smem_u32(Bs) + (uint32_t)(lrow * RS1 + h4) * 4u;

    const uint32_t laneA = (uint32_t)((wm + (lane & 15)) * RS1 +
                                      ((lane >> 4) << 2)) * 4u;
    const uint32_t laneB = (uint32_t)((wn + (lane & 7) + ((lane >> 4) << 3)) * RS1 +
                                      (((lane >> 3) & 1) << 2)) * 4u;
    const uint32_t Abase = smem_u32(As);
    const uint32_t Bbase = smem_u32(Bs);

    float acc[4][4][4];
    #pragma unroll
    for (int mt = 0; mt < 4; mt++)
        #pragma unroll
        for (int nt = 0; nt < 4; nt++)
            #pragma unroll
            for (int q = 0; q < 4; q++) acc[mt][nt][q] = 0.0f;

    #pragma unroll
    for (int s = 0; s < 3; s++) {
        const int kb = s * 32;
        const uint32_t so = (uint32_t)(s * S1_TILE) * 4u;
        cp16(sA + so, eRow + kb);
        cp16(sA + so + 32u, eRow + kb + 16);
        cp16(sB + so, wRow + kb);
        cp16(sB + so + 32u, wRow + kb + 16);
        cp_commit();
    }

    #pragma unroll 1
    for (int it = 0; it < 8; it++) {
        if (it <= 5) cp_wait<2>();
        else if (it == 6) cp_wait<1>();
        else cp_wait<0>();
        __syncthreads();

        if (it < 5) {
            const int s = (it + 3) & 3;
            const int kb = (it + 3) * 32;
            const uint32_t so = (uint32_t)(s * S1_TILE) * 4u;
            cp16(sA + so, eRow + kb);
            cp16(sA + so + 32u, eRow + kb + 16);
            cp16(sB + so, wRow + kb);
            cp16(sB + so + 32u, wRow + kb + 16);
            cp_commit();
        }

        const uint32_t stg = (uint32_t)((it & 3) * S1_TILE) * 4u;
        #pragma unroll
        for (int kk = 0; kk < 2; kk++) {
            const uint32_t kbo = (uint32_t)kk * 32u;
            uint32_t a[4][4], b[2][4];
            #pragma unroll
            for (int mt = 0; mt < 4; mt++)
                ldsm_x4(a[mt], Abase + stg + laneA +
                               (uint32_t)(mt * 16 * RS1) * 4u + kbo);
            #pragma unroll
            for (int j = 0; j < 2; j++)
                ldsm_x4(b[j], Bbase + stg + laneB +
                              (uint32_t)(j * 16 * RS1) * 4u + kbo);
            #pragma unroll
            for (int mt = 0; mt < 4; mt++) {
                mma16816(acc[mt][0], a[mt][0], a[mt][1], a[mt][2], a[mt][3],
                         b[0][0], b[0][1]);
                mma16816(acc[mt][1], a[mt][0], a[mt][1], a[mt][2], a[mt][3],
                         b[0][2], b[0][3]);
                mma16816(acc[mt][2], a[mt][0], a[mt][1], a[mt][2], a[mt][3],
                         b[1][0], b[1][1]);
                mma16816(acc[mt][3], a[mt][0], a[mt][1], a[mt][2], a[mt][3],
                         b[1][2], b[1][3]);
            }
        }
    }

    uint32_t* gb = (uint32_t*)g_bin;
    #pragma unroll
    for (int mt = 0; mt < 4; mt++) {
        const int tA = t0 + wm + mt * 16 + r;
        const size_t row0 = (size_t)tA * (OUTC / 2);
        const size_t row1 = (size_t)(tA + 8) * (OUTC / 2);
        #pragma unroll
        for (int nt = 0; nt < 4; nt++) {
            const int o = o0 + wn + nt * 8 + 2 * qc;
            const float2 bi = *(const float2*)(bias + o);
            float s0 = softplusf(acc[mt][nt][0] + bi.x);
            float s1 = softplusf(acc[mt][nt][1] + bi.y);
            float s2 = softplusf(acc[mt][nt][2] + bi.x);
            float s3 = softplusf(acc[mt][nt][3] + bi.y);
            gb[row0 + (o >> 1)] = pack_bf16(s0, s1);
            gb[row1 + (o >> 1)] = pack_bf16(s2, s3);
        }
    }
}

// ---------------------------------------------------------------------------
// Stage 2: per-token triple contraction, p-row tiling.
//   D[p, y] = sum_h (ex[x(p),h]*ez[z(p),h]) * ey[y,h],  p = x*41+z
//   106 m16 tiles over p (1696 >= 1681), processed as 53 tile-PAIRS per job
//   so 12 ey fragment loads feed 12 MMAs. HMMA/token: 12096 -> 10176.
// ---------------------------------------------------------------------------
#define RS 132
#define EYB 41
#define EZB 89
#define SM2_U32 (137 * RS)
#define SM2_BYTES (SM2_U32 * 4)   // 72336

__global__ void __launch_bounds__(256, 2) triple_mma_kernel(
    const float* __restrict__ ls, float* __restrict__ out)
{
    extern __shared__ uint32_t sm[];
    const int tid = threadIdx.x;
    const int wid = tid >> 5;
    const int lid = tid & 31;
    const int rowin = lid >> 2;   // 0..7
    const int qc = lid & 3;       // 0..3
    const int t = blockIdx.x;

    const uint4* src = (const uint4*)(g_bin + (size_t)t * OUTC);
    for (int i = tid; i < CBIN * 32; i += 256) {
        const int cc = i >> 5;
        const int j = i & 31;
        const int dr = cc + (cc >= 82 ? 7 : 0);
        *(uint4*)&sm[dr * RS + j * 4] = src[i];
    }
    for (int i = tid; i < 7 * RS; i += 256) {
        sm[82 * RS + i] = 0u;     // ey pad rows 82..88 (y = 41..47)
        sm[130 * RS + i] = 0u;    // ez pad (unused after clamp; kept defined)
    }
    __syncthreads();

    const float scale = __expf(ls[0]);
    float* __restrict__ outT = out + (size_t)t * OPT;
    const uint32_t* __restrict__ eyp = sm + (EYB + rowin) * RS;

    // 53 jobs, each = two adjacent m16 p-tiles (rows pb+{0,8,16,24})
    for (int j = wid; j < 53; j += 8) {
        const int pb = 32 * j + rowin;
        const uint32_t* exp_[4];
        const uint32_t* ezp_[4];
        #pragma unroll
        for (int i = 0; i < 4; i++) {
            int p = pb + 8 * i;
            p = (p < NXZ) ? p : (NXZ - 1);   // clamp pad rows
            const int x = p / NB;
            const int z = p - x * NB;
            exp_[i] = sm + x * RS;
            ezp_[i] = sm + (EZB + z) * RS;
        }

        float acc[2][6][4];
        #pragma unroll
        for (int ti = 0; ti < 2; ti++)
            #pragma unroll
            for (int g = 0; g < 6; g++)
                #pragma unroll
                for (int q = 0; q < 4; q++) acc[ti][g][q] = 0.0f;

        #pragma unroll
        for (int k = 0; k < 16; k++) {
            const int c0 = k * 8 + qc;
            const int c1 = c0 + 4;
            // tile A (rows i=0,1), tile B (rows i=2,3)
            const uint32_t A0 = bmul2(exp_[0][c0], ezp_[0][c0]);
            const uint32_t A1 = bmul2(exp_[1][c0], ezp_[1][c0]);
            const uint32_t A2 = bmul2(exp_[0][c1], ezp_[0][c1]);
            const uint32_t A3 = bmul2(exp_[1][c1], ezp_[1][c1]);
            const uint32_t B0 = bmul2(exp_[2][c0], ezp_[2][c0]);
            const uint32_t B1 = bmul2(exp_[3][c0], ezp_[3][c0]);
            const uint32_t B2 = bmul2(exp_[2][c1], ezp_[2][c1]);
            const uint32_t B3 = bmul2(exp_[3][c1], ezp_[3][c1]);
            #pragma unroll
            for (int g = 0; g < 6; g++) {
                const uint32_t b0 = eyp[g * 8 * RS + c0];
                const uint32_t b1 = eyp[g * 8 * RS + c1];
                mma16816(acc[0][g], A0, A1, A2, A3, b0, b1);
                mma16816(acc[1][g], B0, B1, B2, B3, b0, b1);
            }
        }

        // Store: d0=(p_lo,y) d1=(p_lo,y+1) d2=(p_hi,y) d3=(p_hi,y+1)
        #pragma unroll
        for (int ti = 0; ti < 2; ti++) {
            const int p_lo = pb + 16 * ti;
            const int p_hi = p_lo + 8;
            const bool vlo = (p_lo < NXZ);
            const bool vhi = (p_hi < NXZ);
            #pragma unroll
            for (int g = 0; g < 6; g++) {
                const int y = 8 * g + 2 * qc;
                if (y < NB) {
                    float* o = outT + (size_t)y * NXZ;
                    if (vlo) o[p_lo] = acc[ti][g][0] * scale;
                    if (vhi) o[p_hi] = acc[ti][g][2] * scale;
                }
                if (y + 1 < NB) {
                    float* o = outT + (size_t)(y + 1) * NXZ;
                    if (vlo) o[p_lo] = acc[ti][g][1] * scale;
                    if (vhi) o[p_hi] = acc[ti][g][3] * scale;
                }
            }
        }
    }
}

// ---------------------------------------------------------------------------
// Launch (single stream)
// ---------------------------------------------------------------------------
extern "C" void kernel_launch(void* const* d_in, const int* in_sizes, int n_in,
                              void* d_out, int out_size)
{
    const float *emb = nullptr, *W = nullptr, *bias = nullptr, *ls = nullptr;
    for (int i = 0; i < n_in; i++) {
        switch (in_sizes[i]) {
            case TOKENS * HID:   emb  = (const float*)d_in[i]; break;
            case OUTC * HID:     W    = (const float*)d_in[i]; break;
            case OUTC:           bias = (const float*)d_in[i]; break;
            case 1:              ls   = (const float*)d_in[i]; break;
            default: break;
        }
    }

    cvt_bf16_kernel<<<2048, 256>>>(W, emb);

    cudaFuncSetAttribute(gemm_softplus_bf16,
                         cudaFuncAttributeMaxDynamicSharedMemorySize,
                         SM1_BYTES);
    dim3 g1(OUTC / 128, TOKENS / 128);  // 246 x 16
    gemm_softplus_bf16<<<g1, 256, SM1_BYTES>>>(bias);

    cudaFuncSetAttribute(triple_mma_kernel,
                         cudaFuncAttributeMaxDynamicSharedMemorySize,
                         SM2_BYTES);
    triple_mma_kernel<<<TOKENS, 256, SM2_BYTES>>>(ls, (float*)d_out);
}